// round 2
// baseline (speedup 1.0000x reference)
#include <cuda_runtime.h>

// Laplacian_22711787061657
// x: (32, 1, 1024, 1024) fp32. Circular 2nd difference along H and W:
//   gx[h][w] = x[h-2][w] - 2*x[h-1][w] + x[h][w]   (mod 1024)
//   gy[h][w] = x[h][w-2] - 2*x[h][w-1] + x[h][w]   (mod 1024)
//   out = clip(gx+gy, -1, 1) * 0.5, NaN(x)->1.0 on input, NaN->0 on output.
//
// v2: CHUNK=32 (grid 1024 -> more MLP), W-neighbors via shfl_up instead of a
// duplicate row load (lane 0 fetches an 8-byte tail), pointer-increment
// addressing, 0.5 folded into the clamp.

#define HW 1024           // H == W == 1024
#define ROW_F4 (HW / 4)   // 256 float4 per row
#define CHUNK 32          // rows per block
#define NCHUNK (HW / CHUNK)

__device__ __forceinline__ float4 scrub1(float4 v) {
    v.x = isnan(v.x) ? 1.0f : v.x;
    v.y = isnan(v.y) ? 1.0f : v.y;
    v.z = isnan(v.z) ? 1.0f : v.z;
    v.w = isnan(v.w) ? 1.0f : v.w;
    return v;
}

__device__ __forceinline__ float finish(float gx, float gy) {
    // 0.5 * clip(gx+gy, -1, 1) == clamp(0.5*(gx+gy), -0.5, 0.5)
    float g = 0.5f * (gx + gy);
    g = fminf(0.5f, fmaxf(-0.5f, g));
    return isnan(g) ? 0.0f : g;   // remove_nan on output
}

__global__ __launch_bounds__(ROW_F4, 4)
void laplacian_kernel(const float4* __restrict__ x, float4* __restrict__ out) {
    const int t    = threadIdx.x;       // column float4 index, 0..255
    const int lane = t & 31;
    const int chunk = blockIdx.x;       // 0..NCHUNK-1
    const int b     = blockIdx.y;       // image index

    const size_t img_off = (size_t)b * (HW * ROW_F4);
    const float4* __restrict__ xi = x + img_off;
    float4* __restrict__ oi = out + img_off;

    const int tp = (t + ROW_F4 - 1) & (ROW_F4 - 1); // float4 at w-4 (circular)

    const int h0  = chunk * CHUNK;
    const int hm2 = (h0 + HW - 2) & (HW - 1);
    const int hm1 = (h0 + HW - 1) & (HW - 1);

    float4 rm2 = scrub1(xi[(size_t)hm2 * ROW_F4 + t]); // row h-2
    float4 rm1 = scrub1(xi[(size_t)hm1 * ROW_F4 + t]); // row h-1

    const float4* __restrict__ rin  = xi + (size_t)h0 * ROW_F4;
    float4*       __restrict__ rout = oi + (size_t)h0 * ROW_F4;

    #pragma unroll 4
    for (int i = 0; i < CHUNK; ++i) {
        const float4 a = scrub1(rin[t]);   // row h, elements 4t..4t+3

        // W-neighbors (elements 4t-2, 4t-1): from lane-1's a.z/a.w,
        // lane 0 loads the 8-byte tail of float4 (t-1 mod 256) directly.
        float pz = __shfl_up_sync(0xffffffffu, a.z, 1);
        float pw = __shfl_up_sync(0xffffffffu, a.w, 1);
        if (lane == 0) {
            const float2 e = *((const float2*)(rin + tp) + 1);
            pz = isnan(e.x) ? 1.0f : e.x;
            pw = isnan(e.y) ? 1.0f : e.y;
        }

        float4 g;
        g.x = finish(rm2.x - 2.0f * rm1.x + a.x,  pz  - 2.0f * pw  + a.x);
        g.y = finish(rm2.y - 2.0f * rm1.y + a.y,  pw  - 2.0f * a.x + a.y);
        g.z = finish(rm2.z - 2.0f * rm1.z + a.z,  a.x - 2.0f * a.y + a.z);
        g.w = finish(rm2.w - 2.0f * rm1.w + a.w,  a.y - 2.0f * a.z + a.w);

        rout[t] = g;

        rm2 = rm1;
        rm1 = a;
        rin  += ROW_F4;
        rout += ROW_F4;
    }
}

extern "C" void kernel_launch(void* const* d_in, const int* in_sizes, int n_in,
                              void* d_out, int out_size) {
    const float4* x = (const float4*)d_in[0];
    float4* out = (float4*)d_out;
    const int batch = in_sizes[0] / (HW * HW); // 32

    dim3 grid(NCHUNK, batch);
    dim3 block(ROW_F4);
    laplacian_kernel<<<grid, block>>>(x, out);
}